// round 12
// baseline (speedup 1.0000x reference)
#include <cuda_runtime.h>
#include <cuda_fp16.h>
#include <cstdint>

#define Bv 16
#define Cv 64
#define Hv 128
#define Wv 128
#define HCv 64
#define NROWS 2048
#define NSTREAM 148

// W image (fp16): [half(2)][chunk(3)][mloc(128)][k(64) octet-swizzled] = 96 KB
__device__ __align__(16) uint16_t g_wimg[2 * 3 * 128 * 64];
// Pre-rounded X plane (fp16), layout [b][ic][h][w]
#define XN ((size_t)Bv * Cv * Hv * Wv)
__device__ __align__(16) __half g_xhi[XN];

// ---- per-CTA smem map (bytes) ----
// W: 0..49152 (3 x 16KB) ; XBUF: 2 x 16KB at 49152 ; GATES at 81920:
//   [mloc(128)][260B] (stride 65 words == 1 mod 32 -> scan conflict-free)
// PS (fp32 pairs, 2KB) aliased into the consumed X buffer.
#define XB_B   49152
#define GATE_B 81920
#define GROW_B 260
#define SMEM_BYTES 115200

extern __shared__ uint32_t smw[];

__device__ __forceinline__ uint32_t smem_u32(const void* p) {
    uint32_t a;
    asm("{ .reg .u64 t; cvta.to.shared.u64 t, %1; cvt.u32.u64 %0, t; }"
        : "=r"(a) : "l"(p));
    return a;
}

__device__ __forceinline__ float tanh_f(float x) {
    float y;
    asm("tanh.approx.f32 %0, %1;" : "=f"(y) : "f"(x));
    return y;
}
__device__ __forceinline__ float sigmoid_f(float x) {
    return fmaf(tanh_f(0.5f * x), 0.5f, 0.5f);
}

__device__ __forceinline__ void mma_f16(float* c, const uint32_t* a,
                                        uint32_t b0, uint32_t b1) {
    asm volatile(
        "mma.sync.aligned.m16n8k16.row.col.f32.f16.f16.f32 "
        "{%0,%1,%2,%3}, {%4,%5,%6,%7}, {%8,%9}, {%0,%1,%2,%3};\n"
        : "+f"(c[0]), "+f"(c[1]), "+f"(c[2]), "+f"(c[3])
        : "r"(a[0]), "r"(a[1]), "r"(a[2]), "r"(a[3]), "r"(b0), "r"(b1));
}

#define LDM4(R, addr) \
    asm volatile("ldmatrix.sync.aligned.m8n8.x4.shared.b16 {%0,%1,%2,%3}, [%4];" \
        : "=r"((R)[0]), "=r"((R)[1]), "=r"((R)[2]), "=r"((R)[3]) : "r"(addr))
#define LDM4T(R, addr) \
    asm volatile("ldmatrix.sync.aligned.m8n8.x4.trans.shared.b16 {%0,%1,%2,%3}, [%4];" \
        : "=r"((R)[0]), "=r"((R)[1]), "=r"((R)[2]), "=r"((R)[3]) : "r"(addr))
#define CPA16(dst, src) \
    asm volatile("cp.async.ca.shared.global [%0], [%1], 16;" :: "r"(dst), "l"(src))
#define CPA16Z(dst, src, sz) \
    asm volatile("cp.async.ca.shared.global [%0], [%1], 16, %2;" \
                 :: "r"(dst), "l"(src), "r"(sz))
#define CPA_COMMIT() asm volatile("cp.async.commit_group;" ::: "memory")
#define CPA_WAIT0()  asm volatile("cp.async.wait_group 0;" ::: "memory")

__device__ __forceinline__ void sts32(uint32_t a, uint32_t v) {
    asm volatile("st.shared.u32 [%0], %1;" :: "r"(a), "r"(v) : "memory");
}
__device__ __forceinline__ uint32_t lds32(uint32_t a) {
    uint32_t v;
    asm volatile("ld.shared.u32 %0, [%1];" : "=r"(v) : "r"(a));
    return v;
}
__device__ __forceinline__ float2 h2f2(uint32_t w) {
    return __half22float2(*reinterpret_cast<__half2*>(&w));
}

// ---------------------------------------------------------------- prep kernel
__global__ void __launch_bounds__(256)
prep_xw(const float* __restrict__ x, const float* __restrict__ wgt) {
    if (blockIdx.x < 192) {
        int k = blockIdx.x;
        int m = threadIdx.x;
        float v = wgt[m * 192 + k];
        int half = (m >> 5) & 1;
        int mloc = (m >> 6) * 32 + (m & 31);
        int c = k >> 6, kl = k & 63, o = kl >> 3, e = kl & 7;
        g_wimg[((half * 3 + c) * 128 + mloc) * 64 +
               (((o ^ (mloc & 7)) << 3) + e)] =
            __half_as_ushort(__float2half_rn(v));
    }
    size_t i = ((size_t)blockIdx.x * 256 + threadIdx.x) * 8;
    float4 a = *reinterpret_cast<const float4*>(x + i);
    float4 c = *reinterpret_cast<const float4*>(x + i + 4);
    float vf[8] = {a.x, a.y, a.z, a.w, c.x, c.y, c.z, c.w};
    uint32_t hw[4];
#pragma unroll
    for (int j = 0; j < 4; j++) {
        __half2 hh = __float22half2_rn(make_float2(vf[2 * j], vf[2 * j + 1]));
        hw[j] = *reinterpret_cast<uint32_t*>(&hh);
    }
    *reinterpret_cast<uint4*>(g_xhi + i) = make_uint4(hw[0], hw[1], hw[2], hw[3]);
}

// ---------------------------------------------------------------- persistent fused kernel
// 296 CTAs (2/SM), 256 threads = 8 warps (4m x 2n), each CTA owns one hc-half.
// Warp tile 32m x 64w; M=128 (its half's i,f,o,g rows); scan fully local.
__global__ void __launch_bounds__(256, 2)
rowlstm_fused(const float* __restrict__ bias, float* __restrict__ out) {
    const int tid = threadIdx.x;
    const int lane = tid & 31;
    const int wid = tid >> 5;
    const int mw = wid & 3;          // gate index q
    const int nw = wid >> 2;         // 0..1
    const int r = lane >> 2, cl = lane & 3;
    const int half = (blockIdx.x >= NSTREAM) ? 1 : 0;
    const int rs = blockIdx.x - half * NSTREAM;

    const uint32_t smb = smem_u32(smw);

    const int l7 = lane & 7, l15 = lane & 15, lk = lane >> 4;
    const int krl = l7 + ((lane & 16) >> 1);
    const int wo = (lane >> 3) & 1;

    uint64_t gw, gxh;
    asm("cvta.to.global.u64 %0, %1;" : "=l"(gw) : "l"((const void*)g_wimg));
    asm("cvta.to.global.u64 %0, %1;" : "=l"(gxh) : "l"((const void*)g_xhi));
    gw += (uint64_t)half * 49152;

    // bias (global m = mw*64 + half*32 + j)
    float blo[2], bhi[2];
#pragma unroll
    for (int mt = 0; mt < 2; mt++) {
        blo[mt] = bias[mw * 64 + half * 32 + mt * 16 + r];
        bhi[mt] = bias[mw * 64 + half * 32 + mt * 16 + 8 + r];
    }
    const bool isg = (mw == 3);

    // scan mapping: 8 seg x 32 hcl
    const int seg = tid >> 5;
    const int hcl = tid & 31;
    const uint32_t gsc = smb + GATE_B + (uint32_t)hcl * GROW_B + (uint32_t)seg * 32;

#define STAGE_X(bb_, hh_, cn, db)                                           \
    do {                                                                    \
        _Pragma("unroll") for (int t = 0; t < 4; t++) {                     \
            int g = t * 256 + tid;                                          \
            int krow = g >> 4;                                              \
            int woct = g & 15;                                              \
            int kg = (cn) * 64 + krow;                                      \
            int ic = kg / 3;                                                \
            int kh = kg - 3 * ic;                                           \
            int hp = (hh_) + kh - 2;                                        \
            int sz = (hp >= 0) ? 16 : 0;                                    \
            int hpc = (hp >= 0) ? hp : 0;                                   \
            size_t eoff = (((size_t)((bb_) * Cv + ic) * Hv + hpc) * Wv +    \
                           woct * 8) * 2;                                   \
            uint32_t dst = smb + XB_B + (db) * 16384 + krow * 256 +         \
                           ((woct ^ (krow & 7)) << 4);                      \
            CPA16Z(dst, gxh + eoff, sz);                                    \
        }                                                                   \
    } while (0)

    // ---- preamble: W half-image (48KB, once) + first row chunk0
    {
#pragma unroll
        for (int j = 0; j < 12; j++)
            CPA16(smb + tid * 16 + j * 4096, gw + tid * 16 + j * 4096);
        STAGE_X(rs >> 7, rs & 127, 0, 0);
        CPA_COMMIT();
        CPA_WAIT0();
        __syncthreads();
    }

    int p = 0;
#pragma unroll 1
    for (int bh = rs; bh < NROWS; bh += NSTREAM) {
        const int b = bh >> 7, h = bh & 127;

        float acc[2][8][4];
#pragma unroll
        for (int mt = 0; mt < 2; mt++)
#pragma unroll
            for (int nt = 0; nt < 8; nt++)
#pragma unroll
                for (int q = 0; q < 4; q++) acc[mt][nt][q] = 0.0f;

#pragma unroll
        for (int c = 0; c < 3; c++) {
            const int db = (p + c) & 1;
            if (c < 2) {
                STAGE_X(b, h, c + 1, db ^ 1);
                CPA_COMMIT();
            }

            const uint32_t a_h = smb + c * 16384 + (mw * 32 + l15) * 128;
            uint32_t bb[4];
#pragma unroll
            for (int np = 0; np < 4; np++) {
                int oct = nw * 8 + np * 2 + wo;
                bb[np] = smb + XB_B + db * 16384 + krl * 256 + ((oct ^ l7) << 4);
            }
#pragma unroll
            for (int ks = 0; ks < 4; ks++) {
                uint32_t Bh[4][4];
#pragma unroll
                for (int np = 0; np < 4; np++)
                    LDM4T(Bh[np], bb[np] + ks * 4096);
                const uint32_t swA = (uint32_t)(((2 * ks + lk) ^ l7) << 4);
#pragma unroll
                for (int mt = 0; mt < 2; mt++) {
                    uint32_t A[4];
                    LDM4(A, a_h + mt * 2048 + swA);
#pragma unroll
                    for (int nt = 0; nt < 8; nt++) {
                        const int np = nt >> 1, ix = nt & 1;
                        mma_f16(acc[mt][nt], A, Bh[np][ix], Bh[np][2 + ix]);
                    }
                }
            }

            if (c < 2) {
                CPA_WAIT0();
                __syncthreads();
            }
        }

        // prefetch next row chunk0 into buf p^1
        const int nbh = bh + NSTREAM;
        if (nbh < NROWS) {
            STAGE_X(nbh >> 7, nbh & 127, 0, p ^ 1);
            CPA_COMMIT();
        }

        // ---- epilogue: bias + activation -> fp16 gates [mloc][260B]
#pragma unroll
        for (int mt = 0; mt < 2; mt++) {
            const uint32_t glo = smb + GATE_B +
                                 (uint32_t)(mw * 32 + mt * 16 + r) * GROW_B;
            const uint32_t ghi = glo + 8u * GROW_B;
#pragma unroll
            for (int nt = 0; nt < 8; nt++) {
                const uint32_t w2o = (uint32_t)(nw * 32 + nt * 4 + cl) * 4u;
                float v0 = acc[mt][nt][0] + blo[mt];
                float v1 = acc[mt][nt][1] + blo[mt];
                float v2 = acc[mt][nt][2] + bhi[mt];
                float v3 = acc[mt][nt][3] + bhi[mt];
                if (isg) {
                    v0 = tanh_f(v0); v1 = tanh_f(v1);
                    v2 = tanh_f(v2); v3 = tanh_f(v3);
                } else {
                    v0 = sigmoid_f(v0); v1 = sigmoid_f(v1);
                    v2 = sigmoid_f(v2); v3 = sigmoid_f(v3);
                }
                uint32_t p01, p23;
                asm("cvt.rn.f16x2.f32 %0, %1, %2;" : "=r"(p01) : "f"(v1), "f"(v0));
                asm("cvt.rn.f16x2.f32 %0, %1, %2;" : "=r"(p23) : "f"(v3), "f"(v2));
                sts32(glo + w2o, p01);
                sts32(ghi + w2o, p23);
            }
        }
        __syncthreads();

        // ---- LSTM scan: 8 seg x 16 w, 32 hcl; partials in registers
        const uint32_t psb = smb + XB_B + (uint32_t)p * 16384;  // consumed X buf
        float cA[16], PA[16];
        {
            float cc = 0.f, pp = 1.f;
#pragma unroll
            for (int j = 0; j < 8; j++) {
                uint32_t iw = lds32(gsc + 4u * j);
                uint32_t fw = lds32(gsc + 4u * j + 32u * GROW_B);
                uint32_t gg = lds32(gsc + 4u * j + 96u * GROW_B);
                float2 iv = h2f2(iw), fv = h2f2(fw), gv = h2f2(gg);
                cc = fmaf(fv.x, cc, iv.x * gv.x); pp *= fv.x;
                cA[2 * j] = cc; PA[2 * j] = pp;
                cc = fmaf(fv.y, cc, iv.y * gv.y); pp *= fv.y;
                cA[2 * j + 1] = cc; PA[2 * j + 1] = pp;
            }
            uint32_t psa = psb + (uint32_t)(seg * 32 + hcl) * 8;
            asm volatile("st.shared.v2.f32 [%0], {%1, %2};"
                         :: "r"(psa), "f"(pp), "f"(cc) : "memory");
        }
        __syncthreads();

        float cin = 0.f;
#pragma unroll
        for (int s2 = 0; s2 < 7; s2++) {
            if (s2 < seg) {
                uint32_t psa = psb + (uint32_t)(s2 * 32 + hcl) * 8;
                float P, S;
                asm volatile("ld.shared.v2.f32 {%0, %1}, [%2];"
                             : "=f"(P), "=f"(S) : "r"(psa));
                cin = fmaf(P, cin, S);
            }
        }

        {
            float hv[16];
#pragma unroll
            for (int j = 0; j < 8; j++) {
                uint32_t ow = lds32(gsc + 4u * j + 64u * GROW_B);
                float2 ov = h2f2(ow);
                float t0 = fmaf(PA[2 * j], cin, cA[2 * j]);
                float t1 = fmaf(PA[2 * j + 1], cin, cA[2 * j + 1]);
                hv[2 * j] = ov.x * tanh_f(t0);
                hv[2 * j + 1] = ov.y * tanh_f(t1);
            }
            float* po = out + ((size_t)(b * HCv + half * 32 + hcl) * Hv + h) * Wv
                        + seg * 16;
            *reinterpret_cast<float4*>(po) =
                make_float4(hv[0], hv[1], hv[2], hv[3]);
            *reinterpret_cast<float4*>(po + 4) =
                make_float4(hv[4], hv[5], hv[6], hv[7]);
            *reinterpret_cast<float4*>(po + 8) =
                make_float4(hv[8], hv[9], hv[10], hv[11]);
            *reinterpret_cast<float4*>(po + 12) =
                make_float4(hv[12], hv[13], hv[14], hv[15]);
        }

        if (nbh < NROWS) CPA_WAIT0();
        __syncthreads();   // gates consumed; next-row X visible; PS buf freed
        p ^= 1;
    }
}

extern "C" void kernel_launch(void* const* d_in, const int* in_sizes, int n_in,
                              void* d_out, int out_size) {
    const float* x    = (const float*)d_in[0];
    const float* wgt  = (const float*)d_in[1];
    const float* bias = (const float*)d_in[2];
    float* out = (float*)d_out;

    cudaFuncSetAttribute(rowlstm_fused,
                         cudaFuncAttributeMaxDynamicSharedMemorySize, SMEM_BYTES);

    prep_xw<<<8192, 256>>>(x, wgt);
    rowlstm_fused<<<2 * NSTREAM, 256, SMEM_BYTES>>>(bias, out);
}